// round 4
// baseline (speedup 1.0000x reference)
#include <cuda_runtime.h>
#include <math.h>

// Problem constants
#define B_      4096
#define S_SRC_  32
#define S_TGT_  32
#define E_      128
#define H_      512
#define V_TGT_  128
#define G4H_    2048          // 4*H
#define KCAT_   640           // E + H
#define SOS_    1

// ---------------------------------------------------------------------------
// Device scratch (static — no allocations allowed)
// ---------------------------------------------------------------------------
__device__ __align__(16) float g_Wcat_enc[KCAT_ * G4H_];   // [k][gate*H+n]
__device__ __align__(16) float g_Wcat_dec[KCAT_ * G4H_];
__device__ __align__(16) float g_bias_enc[G4H_];
__device__ __align__(16) float g_bias_dec[G4H_];
__device__ __align__(16) float g_WoutT[H_ * V_TGT_];       // [k][v]
__device__ __align__(16) float g_h[2][B_ * H_];            // ping-pong hidden
__device__ __align__(16) float g_c[B_ * H_];               // cell state
__device__ __align__(16) float g_hs[S_TGT_ * B_ * H_];     // decoder hiddens

// ---------------------------------------------------------------------------
// Prep: pack [Wih | Whh]^T, sum biases, transpose W_out, zero h0/c0
// ---------------------------------------------------------------------------
__global__ void prep_kernel(const float* __restrict__ eWih, const float* __restrict__ eWhh,
                            const float* __restrict__ eBih, const float* __restrict__ eBhh,
                            const float* __restrict__ dWih, const float* __restrict__ dWhh,
                            const float* __restrict__ dBih, const float* __restrict__ dBhh,
                            const float* __restrict__ Wout)
{
    int tid = blockIdx.x * blockDim.x + threadIdx.x;
    int stride = gridDim.x * blockDim.x;

    for (int i = tid; i < KCAT_ * G4H_; i += stride) {
        int k = i / G4H_;
        int r = i % G4H_;                 // r = gate*H + n (PyTorch [i,f,g,o] layout)
        g_Wcat_enc[i] = (k < E_) ? eWih[r * E_ + k] : eWhh[r * H_ + (k - E_)];
        g_Wcat_dec[i] = (k < E_) ? dWih[r * E_ + k] : dWhh[r * H_ + (k - E_)];
    }
    for (int i = tid; i < G4H_; i += stride) {
        g_bias_enc[i] = eBih[i] + eBhh[i];
        g_bias_dec[i] = dBih[i] + dBhh[i];
    }
    for (int i = tid; i < H_ * V_TGT_; i += stride) {
        int k = i / V_TGT_, v = i % V_TGT_;
        g_WoutT[i] = Wout[v * H_ + k];
    }
    for (int i = tid; i < B_ * H_; i += stride) {
        g_h[0][i] = 0.0f;
        g_c[i]    = 0.0f;
    }
}

// ---------------------------------------------------------------------------
// Fused LSTM step: gates = [x_t | h_prev] @ Wcat  (+bias)  -> activations ->
// h/c update (masked for encoder). One launch per timestep.
//   Tile: BM=128 batch rows, BN=32 h-cols (x4 gates = 128 weight cols), BK=16.
//   256 threads, 64 fp32 accumulators each.
// ---------------------------------------------------------------------------
template<bool IS_ENC>
__global__ __launch_bounds__(256, 2)
void lstm_step_kernel(int step, int par_src,
                      const int* __restrict__ seq,       // src_seq / tgt_seq
                      const int* __restrict__ lengths,   // src_lengths (enc only)
                      const float* __restrict__ emb)     // emb_src / emb_tgt
{
    __shared__ float a_s[16][128];     // [k][m]
    __shared__ float w_s[16][128];     // [k][c], c = gate*32 + j (j = local n)
    __shared__ int   tok_s[128];

    const float* __restrict__ Wcat = IS_ENC ? g_Wcat_enc : g_Wcat_dec;
    const float* __restrict__ bias = IS_ENC ? g_bias_enc : g_bias_dec;
    const float* __restrict__ h_src = g_h[par_src];
    float* __restrict__ h_dst = g_h[par_src ^ 1];

    const int t  = threadIdx.x;
    const int m0 = blockIdx.x * 128;
    const int n0 = blockIdx.y * 32;

    // token table for this block's 128 batch rows
    if (t < 128) {
        int m = m0 + t;
        int tok;
        if (IS_ENC) tok = seq[m * S_SRC_ + step];
        else        tok = (step == 0) ? SOS_ : seq[m * S_TGT_ + step - 1];
        tok_s[t] = tok;
    }
    __syncthreads();

    // load-thread mapping
    const int lm = t >> 1;                  // 0..127 : A row
    const int lh = t & 1;                   // A k-half (8 floats)
    const int wk = t >> 4;                  // 0..15  : W k row
    const int wl = t & 15;                  // W lane -> 8 cols
    const int wg  = wl >> 2;                // gate 0..3
    const int wj0 = (wl & 3) * 8;           // local n offset

    // compute-thread mapping
    const int tr = t & 15;                  // rows tr*8 .. tr*8+7
    const int tc = t >> 4;                  // n pair: tc*2, tc*2+1

    float acc[8][2][4];
    #pragma unroll
    for (int r = 0; r < 8; r++)
        #pragma unroll
        for (int nn = 0; nn < 2; nn++)
            #pragma unroll
            for (int g = 0; g < 4; g++) acc[r][nn][g] = 0.0f;

    float4 sa0, sa1, sw0, sw1;

    // prologue: stage tile kt=0 (k0=0 -> embedding region)
    {
        const float* ap = emb + tok_s[lm] * E_ + lh * 8;
        sa0 = *(const float4*)ap;
        sa1 = *(const float4*)(ap + 4);
        const float* wp = Wcat + (0 + wk) * G4H_ + wg * H_ + n0 + wj0;
        sw0 = *(const float4*)wp;
        sw1 = *(const float4*)(wp + 4);
    }

    const int NKT = KCAT_ / 16;   // 40
    for (int kt = 0; kt < NKT; kt++) {
        __syncthreads();
        {   // commit staged tile to smem
            int kb = lh * 8;
            a_s[kb + 0][lm] = sa0.x; a_s[kb + 1][lm] = sa0.y;
            a_s[kb + 2][lm] = sa0.z; a_s[kb + 3][lm] = sa0.w;
            a_s[kb + 4][lm] = sa1.x; a_s[kb + 5][lm] = sa1.y;
            a_s[kb + 6][lm] = sa1.z; a_s[kb + 7][lm] = sa1.w;
            *(float4*)&w_s[wk][wl * 8]     = sw0;
            *(float4*)&w_s[wk][wl * 8 + 4] = sw1;
        }
        __syncthreads();

        // prefetch next tile (overlaps with compute below)
        if (kt + 1 < NKT) {
            int k0 = (kt + 1) * 16;
            if (k0 < E_) {
                const float* ap = emb + tok_s[lm] * E_ + k0 + lh * 8;
                sa0 = *(const float4*)ap;
                sa1 = *(const float4*)(ap + 4);
            } else {
                const float* ap = h_src + (m0 + lm) * H_ + (k0 - E_) + lh * 8;
                sa0 = *(const float4*)ap;
                sa1 = *(const float4*)(ap + 4);
            }
            const float* wp = Wcat + (k0 + wk) * G4H_ + wg * H_ + n0 + wj0;
            sw0 = *(const float4*)wp;
            sw1 = *(const float4*)(wp + 4);
        }

        // FFMA mainloop over this BK=16 tile
        #pragma unroll
        for (int kk = 0; kk < 16; kk++) {
            float af[8];
            float4 v0 = *(const float4*)&a_s[kk][tr * 8];
            float4 v1 = *(const float4*)&a_s[kk][tr * 8 + 4];
            af[0] = v0.x; af[1] = v0.y; af[2] = v0.z; af[3] = v0.w;
            af[4] = v1.x; af[5] = v1.y; af[6] = v1.z; af[7] = v1.w;
            float wf[4][2];
            #pragma unroll
            for (int g = 0; g < 4; g++) {
                float2 w2 = *(const float2*)&w_s[kk][g * 32 + tc * 2];
                wf[g][0] = w2.x; wf[g][1] = w2.y;
            }
            #pragma unroll
            for (int r = 0; r < 8; r++)
                #pragma unroll
                for (int nn = 0; nn < 2; nn++)
                    #pragma unroll
                    for (int g = 0; g < 4; g++)
                        acc[r][nn][g] += af[r] * wf[g][nn];
        }
    }

    // ------------------ epilogue: LSTM cell ------------------
    #pragma unroll
    for (int r = 0; r < 8; r++) {
        int m = m0 + tr * 8 + r;
        int len = 0;
        if (IS_ENC) len = lengths[m];
        #pragma unroll
        for (int nn = 0; nn < 2; nn++) {
            int n = n0 + tc * 2 + nn;
            float gi = acc[r][nn][0] + bias[n];
            float gf = acc[r][nn][1] + bias[H_ + n];
            float gg = acc[r][nn][2] + bias[2 * H_ + n];
            float go = acc[r][nn][3] + bias[3 * H_ + n];
            float i_ = 1.0f / (1.0f + expf(-gi));
            float f_ = 1.0f / (1.0f + expf(-gf));
            float g_ = tanhf(gg);
            float o_ = 1.0f / (1.0f + expf(-go));
            int idx = m * H_ + n;
            float c_old = g_c[idx];
            float c_new = f_ * c_old + i_ * g_;
            float h_new = o_ * tanhf(c_new);
            if (IS_ENC && step >= len) {      // pack_padded: freeze past length
                c_new = c_old;
                h_new = h_src[idx];
            }
            g_c[idx]   = c_new;
            h_dst[idx] = h_new;
            if (!IS_ENC) g_hs[step * (B_ * H_) + idx] = h_new;
        }
    }
}

// ---------------------------------------------------------------------------
// Logits: (B*T, H) @ (H, V) + b_out  ->  out[b][t][v]
//   Tile: BM=128, BN=128 (=V), BK=16, 256 threads, 64 accums/thread.
// ---------------------------------------------------------------------------
__global__ __launch_bounds__(256, 2)
void logits_kernel(const float* __restrict__ b_out, float* __restrict__ out)
{
    __shared__ float a_s[16][128];
    __shared__ float w_s[16][128];

    const int t  = threadIdx.x;
    const int m0 = blockIdx.x * 128;     // m = tt*B + b
    const int lm = t >> 1, lh = t & 1;
    const int wk = t >> 4, wl = t & 15;
    const int tr = t & 15, tc = t >> 4;

    float acc[8][8];
    #pragma unroll
    for (int r = 0; r < 8; r++)
        #pragma unroll
        for (int q = 0; q < 8; q++) acc[r][q] = 0.0f;

    float4 sa0, sa1, sw0, sw1;
    {
        const float* ap = g_hs + (m0 + lm) * H_ + lh * 8;
        sa0 = *(const float4*)ap; sa1 = *(const float4*)(ap + 4);
        const float* wp = g_WoutT + wk * V_TGT_ + wl * 8;
        sw0 = *(const float4*)wp; sw1 = *(const float4*)(wp + 4);
    }

    const int NKT = H_ / 16;  // 32
    for (int kt = 0; kt < NKT; kt++) {
        __syncthreads();
        {
            int kb = lh * 8;
            a_s[kb + 0][lm] = sa0.x; a_s[kb + 1][lm] = sa0.y;
            a_s[kb + 2][lm] = sa0.z; a_s[kb + 3][lm] = sa0.w;
            a_s[kb + 4][lm] = sa1.x; a_s[kb + 5][lm] = sa1.y;
            a_s[kb + 6][lm] = sa1.z; a_s[kb + 7][lm] = sa1.w;
            *(float4*)&w_s[wk][wl * 8]     = sw0;
            *(float4*)&w_s[wk][wl * 8 + 4] = sw1;
        }
        __syncthreads();
        if (kt + 1 < NKT) {
            int k0 = (kt + 1) * 16;
            const float* ap = g_hs + (m0 + lm) * H_ + k0 + lh * 8;
            sa0 = *(const float4*)ap; sa1 = *(const float4*)(ap + 4);
            const float* wp = g_WoutT + (k0 + wk) * V_TGT_ + wl * 8;
            sw0 = *(const float4*)wp; sw1 = *(const float4*)(wp + 4);
        }
        #pragma unroll
        for (int kk = 0; kk < 16; kk++) {
            float af[8], wf[8];
            float4 v0 = *(const float4*)&a_s[kk][tr * 8];
            float4 v1 = *(const float4*)&a_s[kk][tr * 8 + 4];
            af[0] = v0.x; af[1] = v0.y; af[2] = v0.z; af[3] = v0.w;
            af[4] = v1.x; af[5] = v1.y; af[6] = v1.z; af[7] = v1.w;
            float4 u0 = *(const float4*)&w_s[kk][tc * 8];
            float4 u1 = *(const float4*)&w_s[kk][tc * 8 + 4];
            wf[0] = u0.x; wf[1] = u0.y; wf[2] = u0.z; wf[3] = u0.w;
            wf[4] = u1.x; wf[5] = u1.y; wf[6] = u1.z; wf[7] = u1.w;
            #pragma unroll
            for (int r = 0; r < 8; r++)
                #pragma unroll
                for (int q = 0; q < 8; q++)
                    acc[r][q] += af[r] * wf[q];
        }
    }

    #pragma unroll
    for (int r = 0; r < 8; r++) {
        int m  = m0 + tr * 8 + r;
        int b  = m & (B_ - 1);
        int tt = m >> 12;                 // B_ = 2^12
        #pragma unroll
        for (int q = 0; q < 8; q++) {
            int v = tc * 8 + q;
            out[(b * S_TGT_ + tt) * V_TGT_ + v] = acc[r][q] + b_out[v];
        }
    }
}

// ---------------------------------------------------------------------------
// Launch
// ---------------------------------------------------------------------------
extern "C" void kernel_launch(void* const* d_in, const int* in_sizes, int n_in,
                              void* d_out, int out_size)
{
    (void)in_sizes; (void)n_in; (void)out_size;
    const int*   src_seq = (const int*)  d_in[0];
    const int*   src_len = (const int*)  d_in[1];
    const int*   tgt_seq = (const int*)  d_in[2];
    const float* emb_src = (const float*)d_in[3];
    const float* eWih    = (const float*)d_in[4];
    const float* eWhh    = (const float*)d_in[5];
    const float* eBih    = (const float*)d_in[6];
    const float* eBhh    = (const float*)d_in[7];
    const float* emb_tgt = (const float*)d_in[8];
    const float* dWih    = (const float*)d_in[9];
    const float* dWhh    = (const float*)d_in[10];
    const float* dBih    = (const float*)d_in[11];
    const float* dBhh    = (const float*)d_in[12];
    const float* Wout    = (const float*)d_in[13];
    const float* bout    = (const float*)d_in[14];
    float*       out     = (float*)d_out;

    prep_kernel<<<2048, 256>>>(eWih, eWhh, eBih, eBhh,
                               dWih, dWhh, dBih, dBhh, Wout);

    dim3 grid(B_ / 128, H_ / 32);   // (32, 16)
    for (int s = 0; s < S_SRC_; s++)
        lstm_step_kernel<true ><<<grid, 256>>>(s, s & 1, src_seq, src_len, emb_src);
    for (int tt = 0; tt < S_TGT_; tt++)
        lstm_step_kernel<false><<<grid, 256>>>(tt, tt & 1, tgt_seq, nullptr, emb_tgt);

    logits_kernel<<<(B_ * S_TGT_) / 128, 256>>>(bout, out);
}